// round 15
// baseline (speedup 1.0000x reference)
#include <cuda_runtime.h>
#include <cuda_bf16.h>
#include <cuda_fp16.h>
#include <math.h>

#define Bz   4
#define NKEY 3136
#define NQ   1568
#define Dm   384
#define Hh   12
#define DH   32
#define BH   (Bz*Hh)
#define D2   768
#define NP   784
#define NKP  3200
#define SM_SCALE 0.17677669529663687f
#define LOG2E    1.4426950408889634f
#define PBIAS    10.0f
#define PSCALE   1024.0f
#define HONES    0x3C003C00u   /* f16x2 {1.0, 1.0} */

typedef __nv_bfloat16 bf16;
typedef __half        f16;

// ---------------- scratch ----------------
__device__ bf16  g_xnb[(size_t)Bz*NKEY*Dm];
__device__ bf16  g_cnb[(size_t)Bz*NQ*Dm];
__device__ bf16  g_Wqb[Dm*Dm];
__device__ bf16  g_Wkvb[Dm*2*Dm];
__device__ bf16  g_Woh[Dm*Dm];
__device__ bf16  g_Wol[Dm*Dm];
__device__ bf16  g_Wph[D2*D2];
__device__ bf16  g_Wpl[D2*D2];
__device__ bf16  g_Qb[(size_t)BH*NQ*DH];
__device__ bf16  g_Kb[(size_t)BH*NKEY*DH];
__device__ f16   g_Vh[(size_t)BH*NKEY*DH];
__device__ float g_l2z[(size_t)BH*NKP];
__device__ bf16  g_c2h[(size_t)Bz*NQ*Dm];
__device__ bf16  g_c2l[(size_t)Bz*NQ*Dm];
__device__ float g_tsh[BH*NQ];
__device__ float g_y0[(size_t)Bz*NQ*Dm];
__device__ bf16  g_ynh[(size_t)Bz*NQ*Dm];
__device__ bf16  g_ynl[(size_t)Bz*NQ*Dm];

// ---------------- helpers ----------------
__device__ __forceinline__ unsigned sm_addr(const void* p) {
    return (unsigned)__cvta_generic_to_shared(p);
}
__device__ __forceinline__ void cp16(void* s, const void* g, int szbytes) {
    unsigned a = sm_addr(s);
    asm volatile("cp.async.ca.shared.global [%0],[%1],16,%2;\n" :: "r"(a), "l"(g), "r"(szbytes));
}
__device__ __forceinline__ void cp_commit() { asm volatile("cp.async.commit_group;\n"); }
template<int N> __device__ __forceinline__ void cp_wait() {
    asm volatile("cp.async.wait_group %0;\n" :: "n"(N));
}
__device__ __forceinline__ void ldsm4(unsigned r[4], const void* p) {
    unsigned a = sm_addr(p);
    asm volatile("ldmatrix.sync.aligned.m8n8.x4.shared.b16 {%0,%1,%2,%3},[%4];\n"
        : "=r"(r[0]),"=r"(r[1]),"=r"(r[2]),"=r"(r[3]) : "r"(a));
}
__device__ __forceinline__ void ldsm4t(unsigned r[4], const void* p) {
    unsigned a = sm_addr(p);
    asm volatile("ldmatrix.sync.aligned.m8n8.x4.trans.shared.b16 {%0,%1,%2,%3},[%4];\n"
        : "=r"(r[0]),"=r"(r[1]),"=r"(r[2]),"=r"(r[3]) : "r"(a));
}
__device__ __forceinline__ void ldsm2t(unsigned r[2], const void* p) {
    unsigned a = sm_addr(p);
    asm volatile("ldmatrix.sync.aligned.m8n8.x2.trans.shared.b16 {%0,%1},[%2];\n"
        : "=r"(r[0]),"=r"(r[1]) : "r"(a));
}
__device__ __forceinline__ void mma_bf16(float c[4], const unsigned a[4], unsigned b0, unsigned b1) {
    asm volatile("mma.sync.aligned.m16n8k16.row.col.f32.bf16.bf16.f32 "
        "{%0,%1,%2,%3},{%4,%5,%6,%7},{%8,%9},{%0,%1,%2,%3};\n"
        : "+f"(c[0]),"+f"(c[1]),"+f"(c[2]),"+f"(c[3])
        : "r"(a[0]),"r"(a[1]),"r"(a[2]),"r"(a[3]),"r"(b0),"r"(b1));
}
__device__ __forceinline__ void mma_f16(float c[4], const unsigned a[4], unsigned b0, unsigned b1) {
    asm volatile("mma.sync.aligned.m16n8k16.row.col.f32.f16.f16.f32 "
        "{%0,%1,%2,%3},{%4,%5,%6,%7},{%8,%9},{%0,%1,%2,%3};\n"
        : "+f"(c[0]),"+f"(c[1]),"+f"(c[2]),"+f"(c[3])
        : "r"(a[0]),"r"(a[1]),"r"(a[2]),"r"(a[3]),"r"(b0),"r"(b1));
}
__device__ __forceinline__ unsigned f2h2(float a, float b) {
    __half2 h = __floats2half2_rn(a, b);
    return *reinterpret_cast<unsigned*>(&h);
}
__device__ __forceinline__ unsigned h2ex2(unsigned x) {
    unsigned r;
    asm("ex2.approx.f16x2 %0,%1;\n" : "=r"(r) : "r"(x));
    return r;
}
template<typename T>
__device__ __forceinline__ const T* lm(const T* base, int lane, int stride) {
    return base + (lane & 15) * stride + (lane >> 4) * 8;
}

// ---------------- prep: fused input LN + weight conversion (one launch) ----------------
#define NW1 (Dm*Dm)
#define NW2 (Dm*2*Dm)
#define NW3 (Dm*Dm)
#define NW4 (D2*D2)
#define NB_LN   (Bz*NKEY + Bz*NQ)
#define NWTOT4  ((NW1 + NW2 + NW3 + NW4) / 4)
#define NB_CVT  ((NWTOT4 + 127) / 128)

__device__ __forceinline__ void cvt_plain4(const float4 v, bf16* d) {
    __nv_bfloat162 h0 = __floats2bfloat162_rn(v.x, v.y);
    __nv_bfloat162 h1 = __floats2bfloat162_rn(v.z, v.w);
    uint2 p;
    p.x = *reinterpret_cast<unsigned*>(&h0);
    p.y = *reinterpret_cast<unsigned*>(&h1);
    *reinterpret_cast<uint2*>(d) = p;
}
__device__ __forceinline__ void cvt_split4(const float4 v, bf16* dh, bf16* dl) {
    __nv_bfloat162 h0 = __floats2bfloat162_rn(v.x, v.y);
    __nv_bfloat162 h1 = __floats2bfloat162_rn(v.z, v.w);
    __nv_bfloat162 l0 = __floats2bfloat162_rn(v.x - __bfloat162float(__low2bfloat16(h0)),
                                              v.y - __bfloat162float(__high2bfloat16(h0)));
    __nv_bfloat162 l1 = __floats2bfloat162_rn(v.z - __bfloat162float(__low2bfloat16(h1)),
                                              v.w - __bfloat162float(__high2bfloat16(h1)));
    uint2 ph, pl;
    ph.x = *reinterpret_cast<unsigned*>(&h0);
    ph.y = *reinterpret_cast<unsigned*>(&h1);
    pl.x = *reinterpret_cast<unsigned*>(&l0);
    pl.y = *reinterpret_cast<unsigned*>(&l1);
    *reinterpret_cast<uint2*>(dh) = ph;
    *reinterpret_cast<uint2*>(dl) = pl;
}

__global__ void prep_kernel(const float* __restrict__ x, const float* __restrict__ clus,
                            const float* __restrict__ g,
                            const float* __restrict__ Wq, const float* __restrict__ Wkv,
                            const float* __restrict__ Wo, const float* __restrict__ Wp)
{
    int blk = blockIdx.x;
    int tid = threadIdx.x;

    if (blk >= NB_LN) {
        int idx4 = (blk - NB_LN) * 128 + tid;
        if (idx4 >= NWTOT4) return;
        int i = idx4 * 4;
        if (i < NW1) {
            cvt_plain4(*reinterpret_cast<const float4*>(Wq + i), &g_Wqb[i]);
            return;
        }
        i -= NW1;
        if (i < NW2) {
            cvt_plain4(*reinterpret_cast<const float4*>(Wkv + i), &g_Wkvb[i]);
            return;
        }
        i -= NW2;
        if (i < NW3) {
            cvt_split4(*reinterpret_cast<const float4*>(Wo + i), &g_Woh[i], &g_Wol[i]);
            return;
        }
        i -= NW3;
        cvt_split4(*reinterpret_cast<const float4*>(Wp + i), &g_Wph[i], &g_Wpl[i]);
        return;
    }

    int row = blk;
    const float* xr;
    bf16* yr;
    if (row < Bz * NKEY) { xr = x + (size_t)row * Dm; yr = g_xnb + (size_t)row * Dm; }
    else { int r = row - Bz * NKEY; xr = clus + (size_t)r * Dm; yr = g_cnb + (size_t)r * Dm; }
    const float4* x4 = reinterpret_cast<const float4*>(xr);
    const float4* g4 = reinterpret_cast<const float4*>(g);
    float s = 0.f, s2 = 0.f;
    for (int i = tid; i < Dm / 4; i += 128) {
        float4 v = x4[i];
        s  += (v.x + v.y) + (v.z + v.w);
        s2 += (v.x * v.x + v.y * v.y) + (v.z * v.z + v.w * v.w);
    }
    __shared__ float sh[64];
    #pragma unroll
    for (int o = 16; o; o >>= 1) {
        s  += __shfl_xor_sync(0xffffffffu, s,  o);
        s2 += __shfl_xor_sync(0xffffffffu, s2, o);
    }
    int w = tid >> 5;
    if ((tid & 31) == 0) { sh[w] = s; sh[32 + w] = s2; }
    __syncthreads();
    if (tid == 0) {
        float a = 0.f, b = 0.f;
        #pragma unroll
        for (int i = 0; i < 4; i++) { a += sh[i]; b += sh[32 + i]; }
        sh[0] = a; sh[32] = b;
    }
    __syncthreads();
    float mu  = sh[0]  / (float)Dm;
    float var = sh[32] / (float)Dm - mu * mu;
    float r = rsqrtf(var + 1e-6f);
    for (int i = tid; i < Dm / 4; i += 128) {
        float4 v = x4[i];
        float4 gv = g4[i];
        __nv_bfloat162 h0 = __floats2bfloat162_rn((v.x - mu) * r * gv.x, (v.y - mu) * r * gv.y);
        __nv_bfloat162 h1 = __floats2bfloat162_rn((v.z - mu) * r * gv.z, (v.w - mu) * r * gv.w);
        uint2 pack;
        pack.x = *reinterpret_cast<unsigned*>(&h0);
        pack.y = *reinterpret_cast<unsigned*>(&h1);
        *reinterpret_cast<uint2*>(yr + i * 4) = pack;
    }
}

// ---------------- LN split (d=768) + fused token-sizes output ----------------
__global__ void ln_split_kernel(const float* __restrict__ x, const float* __restrict__ g,
                                bf16* __restrict__ yh, bf16* __restrict__ yl,
                                float* __restrict__ ts_out)
{
    const int d = D2;
    int row = blockIdx.x;
    int tid = threadIdx.x;

    if (tid == 0) {
        int b = row / NP, p = row - b * NP;
        float sum = 0.f;
        #pragma unroll
        for (int h = 0; h < Hh; h++) {
            const float* t = g_tsh + ((size_t)(b * Hh + h)) * NQ + 2 * p;
            sum += t[0] + t[1];
        }
        ts_out[row] = sum * (1.f / 12.f);
    }

    const float* xr = x + (size_t)row * d;
    const float4* x4 = reinterpret_cast<const float4*>(xr);
    const float4* g4 = reinterpret_cast<const float4*>(g);
    float s = 0.f, s2 = 0.f;
    for (int i = tid; i < d / 4; i += 128) {
        float4 v = x4[i];
        s  += (v.x + v.y) + (v.z + v.w);
        s2 += (v.x * v.x + v.y * v.y) + (v.z * v.z + v.w * v.w);
    }
    __shared__ float sh[64];
    #pragma unroll
    for (int o = 16; o; o >>= 1) {
        s  += __shfl_xor_sync(0xffffffffu, s,  o);
        s2 += __shfl_xor_sync(0xffffffffu, s2, o);
    }
    int w = tid >> 5;
    if ((tid & 31) == 0) { sh[w] = s; sh[32 + w] = s2; }
    __syncthreads();
    if (tid == 0) {
        float a = 0.f, b = 0.f;
        #pragma unroll
        for (int i = 0; i < 4; i++) { a += sh[i]; b += sh[32 + i]; }
        sh[0] = a; sh[32] = b;
    }
    __syncthreads();
    float mu  = sh[0]  / (float)d;
    float var = sh[32] / (float)d - mu * mu;
    float r = rsqrtf(var + 1e-6f);
    for (int i = tid; i < d / 4; i += 128) {
        float4 v = x4[i];
        float4 gv = g4[i];
        float f0 = (v.x - mu) * r * gv.x;
        float f1 = (v.y - mu) * r * gv.y;
        float f2 = (v.z - mu) * r * gv.z;
        float f3 = (v.w - mu) * r * gv.w;
        __nv_bfloat162 h0 = __floats2bfloat162_rn(f0, f1);
        __nv_bfloat162 h1 = __floats2bfloat162_rn(f2, f3);
        __nv_bfloat162 l0 = __floats2bfloat162_rn(f0 - __bfloat162float(__low2bfloat16(h0)),
                                                  f1 - __bfloat162float(__high2bfloat16(h0)));
        __nv_bfloat162 l1 = __floats2bfloat162_rn(f2 - __bfloat162float(__low2bfloat16(h1)),
                                                  f3 - __bfloat162float(__high2bfloat16(h1)));
        uint2 ph, pl;
        ph.x = *reinterpret_cast<unsigned*>(&h0);
        ph.y = *reinterpret_cast<unsigned*>(&h1);
        pl.x = *reinterpret_cast<unsigned*>(&l0);
        pl.y = *reinterpret_cast<unsigned*>(&l1);
        *reinterpret_cast<uint2*>(yh + (size_t)row * d + i * 4) = ph;
        *reinterpret_cast<uint2*>(yl + (size_t)row * d + i * 4) = pl;
    }
}

// ---------------- merged projection GEMM (Q and KV in one launch) ----------------
__global__ void __launch_bounds__(256, 2)
bgemm_merged(const bf16* __restrict__ A0, const bf16* __restrict__ B0,
             const bf16* __restrict__ A1, const bf16* __restrict__ B1)
{
    __shared__ bf16 As[2][128 * 40];
    __shared__ bf16 Bs[2][32 * 136];
    const int tid = threadIdx.x;
    const int w = tid >> 5, lane = tid & 31;
    const int wm = w >> 1, wn = w & 1;

    int bx = blockIdx.x;
    int mode, m0, n0, N;
    const bf16 *A, *Bm;
    if (bx < 147) {
        mode = 0; A = A0; Bm = B0; N = Dm;
        n0 = (bx % 3) * 128; m0 = (bx / 3) * 128;
    } else {
        bx -= 147;
        mode = 1; A = A1; Bm = B1; N = 2 * Dm;
        n0 = (bx % 6) * 128; m0 = (bx / 6) * 128;
    }
    const int K = Dm;

    const int arow0 = (tid + 0)   >> 2, acol0 = ((tid + 0)   & 3) * 8;
    const int arow1 = (tid + 256) >> 2, acol1 = ((tid + 256) & 3) * 8;
    const int brow0 = (tid + 0)   >> 4, bcol0 = ((tid + 0)   & 15) * 8;
    const int brow1 = (tid + 256) >> 4, bcol1 = ((tid + 256) & 15) * 8;

    float acc[2][8][4];
    #pragma unroll
    for (int i = 0; i < 2; i++)
        #pragma unroll
        for (int j = 0; j < 8; j++)
            #pragma unroll
            for (int t = 0; t < 4; t++) acc[i][j][t] = 0.f;

    const int nit = K / 32;
    cp16(&As[0][arow0 * 40 + acol0], A + (size_t)(m0 + arow0) * K + acol0, 16);
    cp16(&As[0][arow1 * 40 + acol1], A + (size_t)(m0 + arow1) * K + acol1, 16);
    cp16(&Bs[0][brow0 * 136 + bcol0], Bm + (size_t)brow0 * N + n0 + bcol0, 16);
    cp16(&Bs[0][brow1 * 136 + bcol1], Bm + (size_t)brow1 * N + n0 + bcol1, 16);
    cp_commit();

    for (int it = 0; it < nit; it++) {
        if (it + 1 < nit) {
            int k0 = (it + 1) * 32, bn = (it + 1) & 1;
            cp16(&As[bn][arow0 * 40 + acol0], A + (size_t)(m0 + arow0) * K + k0 + acol0, 16);
            cp16(&As[bn][arow1 * 40 + acol1], A + (size_t)(m0 + arow1) * K + k0 + acol1, 16);
            cp16(&Bs[bn][brow0 * 136 + bcol0], Bm + (size_t)(k0 + brow0) * N + n0 + bcol0, 16);
            cp16(&Bs[bn][brow1 * 136 + bcol1], Bm + (size_t)(k0 + brow1) * N + n0 + bcol1, 16);
            cp_commit();
            cp_wait<1>();
        } else {
            cp_wait<0>();
        }
        __syncthreads();
        const bf16* Ab = As[it & 1];
        const bf16* Bb = Bs[it & 1];
        #pragma unroll
        for (int kc = 0; kc < 2; kc++) {
            unsigned af[2][4];
            ldsm4(af[0], lm(&Ab[(wm * 32 + 0)  * 40 + kc * 16], lane, 40));
            ldsm4(af[1], lm(&Ab[(wm * 32 + 16) * 40 + kc * 16], lane, 40));
            #pragma unroll
            for (int p = 0; p < 4; p++) {
                unsigned bfr[4];
                ldsm4t(bfr, lm(&Bb[(kc * 16) * 136 + wn * 64 + p * 16], lane, 136));
                #pragma unroll
                for (int mt = 0; mt < 2; mt++) {
                    mma_bf16(acc[mt][2 * p + 0], af[mt], bfr[0], bfr[1]);
                    mma_bf16(acc[mt][2 * p + 1], af[mt], bfr[2], bfr[3]);
                }
            }
        }
        __syncthreads();
    }

    #pragma unroll
    for (int mt = 0; mt < 2; mt++) {
        #pragma unroll
        for (int half = 0; half < 2; half++) {
            int gr = m0 + wm * 32 + mt * 16 + (lane >> 2) + half * 8;
            #pragma unroll
            for (int nb = 0; nb < 8; nb++) {
                int gc = n0 + wn * 64 + nb * 8 + (lane & 3) * 2;
                float v0 = acc[mt][nb][half * 2 + 0];
                float v1 = acc[mt][nb][half * 2 + 1];
                if (mode == 0) {
                    int b = gr / NQ, q = gr - b * NQ;
                    int hh = gc >> 5, di = gc & 31;
                    __nv_bfloat162 hv = __floats2bfloat162_rn(v0 * (SM_SCALE * LOG2E),
                                                              v1 * (SM_SCALE * LOG2E));
                    *reinterpret_cast<__nv_bfloat162*>(
                        &g_Qb[(((size_t)(b * Hh + hh)) * NQ + q) * DH + di]) = hv;
                } else {
                    int b = gr / NKEY, k = gr - b * NKEY;
                    int two = gc >= Dm;
                    int cc = gc - two * Dm;
                    int hh = cc >> 5, di = cc & 31;
                    size_t off = (((size_t)(b * Hh + hh)) * NKEY + k) * DH + di;
                    if (two) {
                        __half2 hv = __floats2half2_rn(v0, v1);
                        *reinterpret_cast<__half2*>(&g_Vh[off]) = hv;
                    } else {
                        __nv_bfloat162 hv = __floats2bfloat162_rn(v0, v1);
                        *reinterpret_cast<__nv_bfloat162*>(&g_Kb[off]) = hv;
                    }
                }
            }
        }
    }
}

// ---------------- split-bf16 compensated GEMM, 128x128 tiles, BK=16 double-buffered ----------------
template<int MODE>
__global__ void __launch_bounds__(256, 2)
bgemm_split(const bf16* __restrict__ Ah, const bf16* __restrict__ Al,
            const bf16* __restrict__ Bh, const bf16* __restrict__ Bl,
            int M, int N, int K,
            const float* __restrict__ res, const float* __restrict__ rscale,
            float* __restrict__ Cout)
{
    __shared__ bf16 Ash[2][128 * 24];
    __shared__ bf16 Asl[2][128 * 24];
    __shared__ bf16 Bsh[2][16 * 136];
    __shared__ bf16 Bsl[2][16 * 136];
    const int tid = threadIdx.x;
    const int w = tid >> 5, lane = tid & 31;
    const int wm = w >> 1, wn = w & 1;
    const int m0 = blockIdx.y * 128, n0 = blockIdx.x * 128;

    const int arow = tid >> 1, acol = (tid & 1) * 8;
    const int brow = tid >> 4, bcol = (tid & 15) * 8;

    float acc[2][8][4];
    #pragma unroll
    for (int i = 0; i < 2; i++)
        #pragma unroll
        for (int j = 0; j < 8; j++)
            #pragma unroll
            for (int t = 0; t < 4; t++) acc[i][j][t] = 0.f;

    const int nit = K / 16;
    {
        int gr = m0 + arow;
        int ok = (gr < M);
        size_t ra = (size_t)(ok ? gr : 0) * K + acol;
        cp16(&Ash[0][arow * 24 + acol], Ah + ra, ok ? 16 : 0);
        cp16(&Asl[0][arow * 24 + acol], Al + ra, ok ? 16 : 0);
        size_t rb = (size_t)brow * N + n0 + bcol;
        cp16(&Bsh[0][brow * 136 + bcol], Bh + rb, 16);
        cp16(&Bsl[0][brow * 136 + bcol], Bl + rb, 16);
        cp_commit();
    }

    for (int it = 0; it < nit; it++) {
        if (it + 1 < nit) {
            int k0 = (it + 1) * 16, bn = (it + 1) & 1;
            int gr = m0 + arow;
            int ok = (gr < M);
            size_t ra = (size_t)(ok ? gr : 0) * K + k0 + acol;
            cp16(&Ash[bn][arow * 24 + acol], Ah + ra, ok ? 16 : 0);
            cp16(&Asl[bn][arow * 24 + acol], Al + ra, ok ? 16 : 0);
            size_t rb = (size_t)(k0 + brow) * N + n0 + bcol;
            cp16(&Bsh[bn][brow * 136 + bcol], Bh + rb, 16);
            cp16(&Bsl[bn][brow * 136 + bcol], Bl + rb, 16);
            cp_commit();
            cp_wait<1>();
        } else {
            cp_wait<0>();
        }
        __syncthreads();
        const bf16* A_h = Ash[it & 1];
        const bf16* A_l = Asl[it & 1];
        const bf16* B_h = Bsh[it & 1];
        const bf16* B_l = Bsl[it & 1];

        unsigned ah[2][4], al[2][4];
        ldsm4(ah[0], lm(&A_h[(wm * 32 + 0)  * 24], lane, 24));
        ldsm4(ah[1], lm(&A_h[(wm * 32 + 16) * 24], lane, 24));
        ldsm4(al[0], lm(&A_l[(wm * 32 + 0)  * 24], lane, 24));
        ldsm4(al[1], lm(&A_l[(wm * 32 + 16) * 24], lane, 24));
        #pragma unroll
        for (int p = 0; p < 4; p++) {
            unsigned bh4[4], bl4[4];
            ldsm4t(bh4, lm(&B_h[wn * 64 + p * 16], lane, 136));
            ldsm4t(bl4, lm(&B_l[wn * 64 + p * 16], lane, 136));
            #pragma unroll
            for (int mt = 0; mt < 2; mt++) {
                mma_bf16(acc[mt][2 * p + 0], ah[mt], bh4[0], bh4[1]);
                mma_bf16(acc[mt][2 * p + 1], ah[mt], bh4[2], bh4[3]);
                mma_bf16(acc[mt][2 * p + 0], ah[mt], bl4[0], bl4[1]);
                mma_bf16(acc[mt][2 * p + 1], ah[mt], bl4[2], bl4[3]);
                mma_bf16(acc[mt][2 * p + 0], al[mt], bh4[0], bh4[1]);
                mma_bf16(acc[mt][2 * p + 1], al[mt], bh4[2], bh4[3]);
            }
        }
        __syncthreads();
    }

    #pragma unroll
    for (int mt = 0; mt < 2; mt++) {
        #pragma unroll
        for (int half = 0; half < 2; half++) {
            int gr = m0 + wm * 32 + mt * 16 + (lane >> 2) + half * 8;
            if (gr >= M) continue;
            #pragma unroll
            for (int nb = 0; nb < 8; nb++) {
                int gc = n0 + wn * 64 + nb * 8 + (lane & 3) * 2;
                float v0 = acc[mt][nb][half * 2 + 0];
                float v1 = acc[mt][nb][half * 2 + 1];
                if (MODE == 2) {
                    v0 += res[(size_t)gr * N + gc + 0] * rscale[gc + 0];
                    v1 += res[(size_t)gr * N + gc + 1] * rscale[gc + 1];
                }
                *reinterpret_cast<float2*>(&Cout[(size_t)gr * N + gc]) = make_float2(v0, v1);
            }
        }
    }
}

// ---------------- Z-pass: 128-key tile, ones-mma, triple-buffered Q ----------------
__global__ void __launch_bounds__(256)
zpass()
{
    __shared__ bf16 Ks[128 * 40];
    __shared__ bf16 Qs[3][128 * 40];
    const int tid = threadIdx.x;
    const int w = tid >> 5, lane = tid & 31;
    const int k0 = blockIdx.x * 128;
    const int bh = blockIdx.y;

    #pragma unroll
    for (int i = 0; i < 2; i++) {
        int idx = tid + 256 * i;
        int row = idx >> 2, col = (idx & 3) * 8;
        uint4 v = make_uint4(0, 0, 0, 0);
        int kg = k0 + row;
        if (kg < NKEY) v = *reinterpret_cast<const uint4*>(&g_Kb[((size_t)bh * NKEY + kg) * DH + col]);
        *reinterpret_cast<uint4*>(&Ks[row * 40 + col]) = v;
    }
    __syncthreads();

    unsigned aK[2][4];
    ldsm4(aK[0], lm(&Ks[(w * 16) * 40 + 0],  lane, 40));
    ldsm4(aK[1], lm(&Ks[(w * 16) * 40 + 16], lane, 40));

    float zacc[4] = {0.f, 0.f, 0.f, 0.f};

    const int qrow = tid >> 2, qcol = (tid & 3) * 8;
    const int qrow1 = (tid + 256) >> 2, qcol1 = ((tid + 256) & 3) * 8;
    {
        int ok = (qrow < NQ);
        cp16(&Qs[0][qrow * 40 + qcol], &g_Qb[((size_t)bh * NQ + (ok ? qrow : 0)) * DH + qcol], ok ? 16 : 0);
        int ok1 = (qrow1 < NQ);
        cp16(&Qs[0][qrow1 * 40 + qcol1], &g_Qb[((size_t)bh * NQ + (ok1 ? qrow1 : 0)) * DH + qcol1], ok1 ? 16 : 0);
        cp_commit();
    }

    for (int qc = 0; qc < 13; qc++) {
        if (qc + 1 < 13) {
            int qt = (qc + 1) * 128;
            int bn = (qc + 1) % 3;
            int qg = qt + qrow;
            int ok = (qg < NQ);
            cp16(&Qs[bn][qrow * 40 + qcol], &g_Qb[((size_t)bh * NQ + (ok ? qg : 0)) * DH + qcol], ok ? 16 : 0);
            int qg1 = qt + qrow1;
            int ok1 = (qg1 < NQ);
            cp16(&Qs[bn][qrow1 * 40 + qcol1], &g_Qb[((size_t)bh * NQ + (ok1 ? qg1 : 0)) * DH + qcol1], ok1 ? 16 : 0);
            cp_commit();
            cp_wait<1>();
        } else {
            cp_wait<0>();
        }
        __syncthreads();

        const bf16* Qb = Qs[qc % 3];
        int q0 = qc * 128;
        #pragma unroll
        for (int nb2 = 0; nb2 < 8; nb2++) {
            if (q0 + nb2 * 16 >= NQ) continue;
            unsigned bA[4], bB[4];
            ldsm4(bA, lm(&Qb[(nb2 * 16) * 40 + 0],  lane, 40));
            ldsm4(bB, lm(&Qb[(nb2 * 16) * 40 + 16], lane, 40));
            unsigned pa[4];
            #pragma unroll
            for (int s = 0; s < 2; s++) {
                float c[4] = {0.f, 0.f, 0.f, 0.f};
                mma_bf16(c, aK[0], bA[s], bA[s + 2]);
                mma_bf16(c, aK[1], bB[s], bB[s + 2]);
                pa[2 * s + 0] = h2ex2(f2h2(c[0], c[1]));
                pa[2 * s + 1] = h2ex2(f2h2(c[2], c[3]));
            }
            unsigned af[4] = {pa[0], pa[1], pa[2], pa[3]};
            mma_f16(zacc, af, HONES, HONES);
        }
    }

    if ((lane & 3) == 0) {
        int r0 = k0 + w * 16 + (lane >> 2);
        int r1 = r0 + 8;
        g_l2z[(size_t)bh * NKP + r0] = (r0 < NKEY) ? (PBIAS - __log2f(zacc[0])) : -1e30f;
        g_l2z[(size_t)bh * NKP + r1] = (r1 < NKEY) ? (PBIAS - __log2f(zacc[2])) : -1e30f;
    }
}

// ---------------- PV-pass: fused per-16-key-block S->exp->PV (low register pressure) ----------------
__global__ void __launch_bounds__(256)
pvpass()
{
    __shared__ bf16 Ks[2][128 * 40];
    __shared__ f16  Vs[2][128 * 40];
    __shared__ float l2zs[2][128];
    const int tid = threadIdx.x;
    const int w = tid >> 5, lane = tid & 31;
    const int q0 = blockIdx.x * 128;
    const int bh = blockIdx.y;
    const int b = bh / Hh, hh = bh % Hh;

    {
        int r = tid >> 1;
        int cb = 32 + (tid & 1) * 4;
        f16 vals[4];
        vals[0] = (cb == 32) ? __float2half(1.f) : __float2half(0.f);
        vals[1] = vals[2] = vals[3] = __float2half(0.f);
        *reinterpret_cast<uint2*>(&Vs[0][r * 40 + cb]) = *reinterpret_cast<uint2*>(vals);
        *reinterpret_cast<uint2*>(&Vs[1][r * 40 + cb]) = *reinterpret_cast<uint2*>(vals);
    }

    #pragma unroll
    for (int i = 0; i < 2; i++) {
        int idx = tid + 256 * i;
        int row = idx >> 2, col = (idx & 3) * 8;
        uint4 v = make_uint4(0, 0, 0, 0);
        int qg = q0 + row;
        if (qg < NQ) v = *reinterpret_cast<const uint4*>(&g_Qb[((size_t)bh * NQ + qg) * DH + col]);
        *reinterpret_cast<uint4*>(&Ks[0][row * 40 + col]) = v;
    }
    __syncthreads();
    unsigned aQ[2][4];
    ldsm4(aQ[0], lm(&Ks[0][(w * 16) * 40 + 0],  lane, 40));
    ldsm4(aQ[1], lm(&Ks[0][(w * 16) * 40 + 16], lane, 40));
    __syncthreads();

    float acc[5][4];
    #pragma unroll
    for (int i = 0; i < 5; i++)
        #pragma unroll
        for (int t = 0; t < 4; t++) acc[i][t] = 0.f;

    #pragma unroll
    for (int i = 0; i < 2; i++) {
        int idx = tid + 256 * i;
        int row = idx >> 2, col = (idx & 3) * 8;
        int kg = row;
        int ok = (kg < NKEY);
        size_t ka = ((size_t)bh * NKEY + (ok ? kg : 0)) * DH + col;
        cp16(&Ks[0][row * 40 + col], &g_Kb[ka], ok ? 16 : 0);
        cp16(&Vs[0][row * 40 + col], &g_Vh[ka], ok ? 16 : 0);
    }
    if (tid < 32) cp16(&l2zs[0][tid * 4], &g_l2z[(size_t)bh * NKP + tid * 4], 16);
    cp_commit();

    for (int kt = 0; kt < 25; kt++) {
        if (kt + 1 < 25) {
            int kb = (kt + 1) * 128;
            int bufn = (kt + 1) & 1;
            #pragma unroll
            for (int i = 0; i < 2; i++) {
                int idx = tid + 256 * i;
                int row = idx >> 2, col = (idx & 3) * 8;
                int kg = kb + row;
                int ok = (kg < NKEY);
                size_t ka = ((size_t)bh * NKEY + (ok ? kg : 0)) * DH + col;
                cp16(&Ks[bufn][row * 40 + col], &g_Kb[ka], ok ? 16 : 0);
                cp16(&Vs[bufn][row * 40 + col], &g_Vh[ka], ok ? 16 : 0);
            }
            if (tid < 32) cp16(&l2zs[bufn][tid * 4], &g_l2z[(size_t)bh * NKP + kb + tid * 4], 16);
            cp_commit();
            cp_wait<1>();
        } else {
            cp_wait<0>();
        }
        __syncthreads();

        const bf16* Kb = Ks[kt & 1];
        const f16*  Vb = Vs[kt & 1];
        const float* lz = l2zs[kt & 1];

        // fused: per 16-key block, S-mma -> exp -> PV-mma (pa live for one block only)
        #pragma unroll
        for (int kb2 = 0; kb2 < 8; kb2++) {
            unsigned bA[4], bB[4];
            ldsm4(bA, lm(&Kb[(kb2 * 16) * 40 + 0],  lane, 40));
            ldsm4(bB, lm(&Kb[(kb2 * 16) * 40 + 16], lane, 40));
            int cb = kb2 * 16 + (lane & 3) * 2;
            float b0 = lz[cb], b1 = lz[cb + 1], b2 = lz[cb + 8], b3 = lz[cb + 9];
            float c0[4] = {b0, b1, b0, b1};
            float c1[4] = {b2, b3, b2, b3};
            mma_bf16(c0, aQ[0], bA[0], bA[2]);
            mma_bf16(c0, aQ[1], bB[0], bB[2]);
            mma_bf16(c1, aQ[0], bA[1], bA[3]);
            mma_bf16(c1, aQ[1], bB[1], bB[3]);
            unsigned pa[4];
            pa[0] = h2ex2(f2h2(c0[0], c0[1]));
            pa[1] = h2ex2(f2h2(c0[2], c0[3]));
            pa[2] = h2ex2(f2h2(c1[0], c1[1]));
            pa[3] = h2ex2(f2h2(c1[2], c1[3]));
            unsigned v0[4], v1[4], v2[2];
            ldsm4t(v0, lm(&Vb[(kb2 * 16) * 40 + 0],  lane, 40));
            ldsm4t(v1, lm(&Vb[(kb2 * 16) * 40 + 16], lane, 40));
            ldsm2t(v2, lm(&Vb[(kb2 * 16) * 40 + 32], lane, 40));
            mma_f16(acc[0], pa, v0[0], v0[1]);
            mma_f16(acc[1], pa, v0[2], v0[3]);
            mma_f16(acc[2], pa, v1[0], v1[1]);
            mma_f16(acc[3], pa, v1[2], v1[3]);
            mma_f16(acc[4], pa, v2[0], v2[1]);
        }
        __syncthreads();
    }

    int src = lane & 28;
    float den0 = __shfl_sync(0xffffffffu, acc[4][0], src);
    float den1 = __shfl_sync(0xffffffffu, acc[4][2], src);
    float inv0 = 1.f / (den0 + PSCALE * 1e-6f);
    float inv1 = 1.f / (den1 + PSCALE * 1e-6f);

    int qr0 = q0 + w * 16 + (lane >> 2);
    int qr1 = qr0 + 8;
    if (qr0 < NQ) {
        size_t base = ((size_t)b * NQ + qr0) * Dm + hh * DH + (lane & 3) * 2;
        #pragma unroll
        for (int nb = 0; nb < 4; nb++) {
            float v0 = acc[nb][0] * inv0, v1 = acc[nb][1] * inv0;
            __nv_bfloat162 h = __floats2bfloat162_rn(v0, v1);
            __nv_bfloat162 l = __floats2bfloat162_rn(v0 - __bfloat162float(__low2bfloat16(h)),
                                                     v1 - __bfloat162float(__high2bfloat16(h)));
            *reinterpret_cast<__nv_bfloat162*>(&g_c2h[base + nb * 8]) = h;
            *reinterpret_cast<__nv_bfloat162*>(&g_c2l[base + nb * 8]) = l;
        }
        if ((lane & 3) == 0) g_tsh[(size_t)bh * NQ + qr0] = den0 * (1.f / PSCALE);
    }
    if (qr1 < NQ) {
        size_t base = ((size_t)b * NQ + qr1) * Dm + hh * DH + (lane & 3) * 2;
        #pragma unroll
        for (int nb = 0; nb < 4; nb++) {
            float v0 = acc[nb][2] * inv1, v1 = acc[nb][3] * inv1;
            __nv_bfloat162 h = __floats2bfloat162_rn(v0, v1);
            __nv_bfloat162 l = __floats2bfloat162_rn(v0 - __bfloat162float(__low2bfloat16(h)),
                                                     v1 - __bfloat162float(__high2bfloat16(h)));
            *reinterpret_cast<__nv_bfloat162*>(&g_c2h[base + nb * 8]) = h;
            *reinterpret_cast<__nv_bfloat162*>(&g_c2l[base + nb * 8]) = l;
        }
        if ((lane & 3) == 0) g_tsh[(size_t)bh * NQ + qr1] = den1 * (1.f / PSCALE);
    }
}

// ---------------- launch ----------------
extern "C" void kernel_launch(void* const* d_in, const int* in_sizes, int n_in,
                              void* d_out, int out_size)
{
    const float* x         = (const float*)d_in[0];
    const float* clusters  = (const float*)d_in[1];
    const float* g1        = (const float*)d_in[2];
    const float* Wq        = (const float*)d_in[3];
    const float* Wkv       = (const float*)d_in[4];
    const float* Wo        = (const float*)d_in[5];
    const float* res_scale = (const float*)d_in[6];
    const float* g2        = (const float*)d_in[7];
    const float* Wproj     = (const float*)d_in[8];
    float* out = (float*)d_out;

    bf16 *p_xnb, *p_cnb, *p_Wqb, *p_Wkvb, *p_Woh, *p_Wol, *p_Wph, *p_Wpl;
    bf16 *p_c2h, *p_c2l, *p_ynh, *p_ynl;
    float *p_y0;
    cudaGetSymbolAddress((void**)&p_xnb, g_xnb);
    cudaGetSymbolAddress((void**)&p_cnb, g_cnb);
    cudaGetSymbolAddress((void**)&p_Wqb, g_Wqb);
    cudaGetSymbolAddress((void**)&p_Wkvb, g_Wkvb);
    cudaGetSymbolAddress((void**)&p_Woh, g_Woh);
    cudaGetSymbolAddress((void**)&p_Wol, g_Wol);
    cudaGetSymbolAddress((void**)&p_Wph, g_Wph);
    cudaGetSymbolAddress((void**)&p_Wpl, g_Wpl);
    cudaGetSymbolAddress((void**)&p_c2h, g_c2h);
    cudaGetSymbolAddress((void**)&p_c2l, g_c2l);
    cudaGetSymbolAddress((void**)&p_ynh, g_ynh);
    cudaGetSymbolAddress((void**)&p_ynl, g_ynl);
    cudaGetSymbolAddress((void**)&p_y0, g_y0);

    prep_kernel<<<NB_LN + NB_CVT, 128>>>(x, clusters, g1, Wq, Wkv, Wo, Wproj);

    bgemm_merged<<<735, 256>>>(p_cnb, p_Wqb, p_xnb, p_Wkvb);

    zpass<<<dim3(25, BH), 256>>>();
    pvpass<<<dim3(13, BH), 256>>>();

    bgemm_split<2><<<dim3(3, 49), 256>>>(p_c2h, p_c2l, p_Woh, p_Wol,
                                         Bz * NQ, Dm, Dm, clusters, res_scale, p_y0);
    ln_split_kernel<<<Bz * NP, 128>>>(p_y0, g2, p_ynh, p_ynl, out + (size_t)Bz * NP * D2);
    bgemm_split<3><<<dim3(6, 25), 256>>>(p_ynh, p_ynl, p_Wph, p_Wpl,
                                         Bz * NP, D2, D2, nullptr, nullptr, out);
}

// round 16
// speedup vs baseline: 1.0739x; 1.0739x over previous
#include <cuda_runtime.h>
#include <cuda_bf16.h>
#include <cuda_fp16.h>
#include <math.h>

#define Bz   4
#define NKEY 3136
#define NQ   1568
#define Dm   384
#define Hh   12
#define DH   32
#define BH   (Bz*Hh)
#define D2   768
#define NP   784
#define NKP  3200
#define SM_SCALE 0.17677669529663687f
#define LOG2E    1.4426950408889634f
#define PBIAS    10.0f
#define PSCALE   1024.0f
#define HONES    0x3C003C00u   /* f16x2 {1.0, 1.0} */

typedef __nv_bfloat16 bf16;
typedef __half        f16;

// ---------------- scratch ----------------
__device__ bf16  g_xnb[(size_t)Bz*NKEY*Dm];
__device__ bf16  g_cnb[(size_t)Bz*NQ*Dm];
__device__ bf16  g_Wqb[Dm*Dm];
__device__ bf16  g_Wkvb[Dm*2*Dm];
__device__ bf16  g_Woh[Dm*Dm];
__device__ bf16  g_Wol[Dm*Dm];
__device__ bf16  g_Wph[D2*D2];
__device__ bf16  g_Wpl[D2*D2];
__device__ bf16  g_Qb[(size_t)BH*NQ*DH];
__device__ bf16  g_Kb[(size_t)BH*NKEY*DH];
__device__ f16   g_Vh[(size_t)BH*NKEY*DH];
__device__ float g_l2z[(size_t)BH*NKP];
__device__ bf16  g_c2h[(size_t)Bz*NQ*Dm];
__device__ bf16  g_c2l[(size_t)Bz*NQ*Dm];
__device__ float g_tsh[BH*NQ];
__device__ float g_y0[(size_t)Bz*NQ*Dm];
__device__ bf16  g_ynh[(size_t)Bz*NQ*Dm];
__device__ bf16  g_ynl[(size_t)Bz*NQ*Dm];

// ---------------- helpers ----------------
__device__ __forceinline__ unsigned sm_addr(const void* p) {
    return (unsigned)__cvta_generic_to_shared(p);
}
__device__ __forceinline__ void cp16(void* s, const void* g, int szbytes) {
    unsigned a = sm_addr(s);
    asm volatile("cp.async.ca.shared.global [%0],[%1],16,%2;\n" :: "r"(a), "l"(g), "r"(szbytes));
}
__device__ __forceinline__ void cp_commit() { asm volatile("cp.async.commit_group;\n"); }
template<int N> __device__ __forceinline__ void cp_wait() {
    asm volatile("cp.async.wait_group %0;\n" :: "n"(N));
}
__device__ __forceinline__ void ldsm4(unsigned r[4], const void* p) {
    unsigned a = sm_addr(p);
    asm volatile("ldmatrix.sync.aligned.m8n8.x4.shared.b16 {%0,%1,%2,%3},[%4];\n"
        : "=r"(r[0]),"=r"(r[1]),"=r"(r[2]),"=r"(r[3]) : "r"(a));
}
__device__ __forceinline__ void ldsm4t(unsigned r[4], const void* p) {
    unsigned a = sm_addr(p);
    asm volatile("ldmatrix.sync.aligned.m8n8.x4.trans.shared.b16 {%0,%1,%2,%3},[%4];\n"
        : "=r"(r[0]),"=r"(r[1]),"=r"(r[2]),"=r"(r[3]) : "r"(a));
}
__device__ __forceinline__ void ldsm2t(unsigned r[2], const void* p) {
    unsigned a = sm_addr(p);
    asm volatile("ldmatrix.sync.aligned.m8n8.x2.trans.shared.b16 {%0,%1},[%2];\n"
        : "=r"(r[0]),"=r"(r[1]) : "r"(a));
}
__device__ __forceinline__ void mma_bf16(float c[4], const unsigned a[4], unsigned b0, unsigned b1) {
    asm volatile("mma.sync.aligned.m16n8k16.row.col.f32.bf16.bf16.f32 "
        "{%0,%1,%2,%3},{%4,%5,%6,%7},{%8,%9},{%0,%1,%2,%3};\n"
        : "+f"(c[0]),"+f"(c[1]),"+f"(c[2]),"+f"(c[3])
        : "r"(a[0]),"r"(a[1]),"r"(a[2]),"r"(a[3]),"r"(b0),"r"(b1));
}
__device__ __forceinline__ void mma_f16(float c[4], const unsigned a[4], unsigned b0, unsigned b1) {
    asm volatile("mma.sync.aligned.m16n8k16.row.col.f32.f16.f16.f32 "
        "{%0,%1,%2,%3},{%4,%5,%6,%7},{%8,%9},{%0,%1,%2,%3};\n"
        : "+f"(c[0]),"+f"(c[1]),"+f"(c[2]),"+f"(c[3])
        : "r"(a[0]),"r"(a[1]),"r"(a[2]),"r"(a[3]),"r"(b0),"r"(b1));
}
__device__ __forceinline__ unsigned f2h2(float a, float b) {
    __half2 h = __floats2half2_rn(a, b);
    return *reinterpret_cast<unsigned*>(&h);
}
__device__ __forceinline__ unsigned h2ex2(unsigned x) {
    unsigned r;
    asm("ex2.approx.f16x2 %0,%1;\n" : "=r"(r) : "r"(x));
    return r;
}
template<typename T>
__device__ __forceinline__ const T* lm(const T* base, int lane, int stride) {
    return base + (lane & 15) * stride + (lane >> 4) * 8;
}

// ---------------- prep: fused input LN + weight conversion (one launch) ----------------
#define NW1 (Dm*Dm)
#define NW2 (Dm*2*Dm)
#define NW3 (Dm*Dm)
#define NW4 (D2*D2)
#define NB_LN   (Bz*NKEY + Bz*NQ)
#define NWTOT4  ((NW1 + NW2 + NW3 + NW4) / 4)
#define NB_CVT  ((NWTOT4 + 127) / 128)

__device__ __forceinline__ void cvt_plain4(const float4 v, bf16* d) {
    __nv_bfloat162 h0 = __floats2bfloat162_rn(v.x, v.y);
    __nv_bfloat162 h1 = __floats2bfloat162_rn(v.z, v.w);
    uint2 p;
    p.x = *reinterpret_cast<unsigned*>(&h0);
    p.y = *reinterpret_cast<unsigned*>(&h1);
    *reinterpret_cast<uint2*>(d) = p;
}
__device__ __forceinline__ void cvt_split4(const float4 v, bf16* dh, bf16* dl) {
    __nv_bfloat162 h0 = __floats2bfloat162_rn(v.x, v.y);
    __nv_bfloat162 h1 = __floats2bfloat162_rn(v.z, v.w);
    __nv_bfloat162 l0 = __floats2bfloat162_rn(v.x - __bfloat162float(__low2bfloat16(h0)),
                                              v.y - __bfloat162float(__high2bfloat16(h0)));
    __nv_bfloat162 l1 = __floats2bfloat162_rn(v.z - __bfloat162float(__low2bfloat16(h1)),
                                              v.w - __bfloat162float(__high2bfloat16(h1)));
    uint2 ph, pl;
    ph.x = *reinterpret_cast<unsigned*>(&h0);
    ph.y = *reinterpret_cast<unsigned*>(&h1);
    pl.x = *reinterpret_cast<unsigned*>(&l0);
    pl.y = *reinterpret_cast<unsigned*>(&l1);
    *reinterpret_cast<uint2*>(dh) = ph;
    *reinterpret_cast<uint2*>(dl) = pl;
}

__global__ void prep_kernel(const float* __restrict__ x, const float* __restrict__ clus,
                            const float* __restrict__ g,
                            const float* __restrict__ Wq, const float* __restrict__ Wkv,
                            const float* __restrict__ Wo, const float* __restrict__ Wp)
{
    int blk = blockIdx.x;
    int tid = threadIdx.x;

    if (blk >= NB_LN) {
        int idx4 = (blk - NB_LN) * 128 + tid;
        if (idx4 >= NWTOT4) return;
        int i = idx4 * 4;
        if (i < NW1) {
            cvt_plain4(*reinterpret_cast<const float4*>(Wq + i), &g_Wqb[i]);
            return;
        }
        i -= NW1;
        if (i < NW2) {
            cvt_plain4(*reinterpret_cast<const float4*>(Wkv + i), &g_Wkvb[i]);
            return;
        }
        i -= NW2;
        if (i < NW3) {
            cvt_split4(*reinterpret_cast<const float4*>(Wo + i), &g_Woh[i], &g_Wol[i]);
            return;
        }
        i -= NW3;
        cvt_split4(*reinterpret_cast<const float4*>(Wp + i), &g_Wph[i], &g_Wpl[i]);
        return;
    }

    int row = blk;
    const float* xr;
    bf16* yr;
    if (row < Bz * NKEY) { xr = x + (size_t)row * Dm; yr = g_xnb + (size_t)row * Dm; }
    else { int r = row - Bz * NKEY; xr = clus + (size_t)r * Dm; yr = g_cnb + (size_t)r * Dm; }
    const float4* x4 = reinterpret_cast<const float4*>(xr);
    const float4* g4 = reinterpret_cast<const float4*>(g);
    float s = 0.f, s2 = 0.f;
    for (int i = tid; i < Dm / 4; i += 128) {
        float4 v = x4[i];
        s  += (v.x + v.y) + (v.z + v.w);
        s2 += (v.x * v.x + v.y * v.y) + (v.z * v.z + v.w * v.w);
    }
    __shared__ float sh[64];
    #pragma unroll
    for (int o = 16; o; o >>= 1) {
        s  += __shfl_xor_sync(0xffffffffu, s,  o);
        s2 += __shfl_xor_sync(0xffffffffu, s2, o);
    }
    int w = tid >> 5;
    if ((tid & 31) == 0) { sh[w] = s; sh[32 + w] = s2; }
    __syncthreads();
    if (tid == 0) {
        float a = 0.f, b = 0.f;
        #pragma unroll
        for (int i = 0; i < 4; i++) { a += sh[i]; b += sh[32 + i]; }
        sh[0] = a; sh[32] = b;
    }
    __syncthreads();
    float mu  = sh[0]  / (float)Dm;
    float var = sh[32] / (float)Dm - mu * mu;
    float r = rsqrtf(var + 1e-6f);
    for (int i = tid; i < Dm / 4; i += 128) {
        float4 v = x4[i];
        float4 gv = g4[i];
        __nv_bfloat162 h0 = __floats2bfloat162_rn((v.x - mu) * r * gv.x, (v.y - mu) * r * gv.y);
        __nv_bfloat162 h1 = __floats2bfloat162_rn((v.z - mu) * r * gv.z, (v.w - mu) * r * gv.w);
        uint2 pack;
        pack.x = *reinterpret_cast<unsigned*>(&h0);
        pack.y = *reinterpret_cast<unsigned*>(&h1);
        *reinterpret_cast<uint2*>(yr + i * 4) = pack;
    }
}

// ---------------- LN split (d=768) + fused token-sizes output ----------------
__global__ void ln_split_kernel(const float* __restrict__ x, const float* __restrict__ g,
                                bf16* __restrict__ yh, bf16* __restrict__ yl,
                                float* __restrict__ ts_out)
{
    const int d = D2;
    int row = blockIdx.x;
    int tid = threadIdx.x;

    if (tid == 0) {
        int b = row / NP, p = row - b * NP;
        float sum = 0.f;
        #pragma unroll
        for (int h = 0; h < Hh; h++) {
            const float* t = g_tsh + ((size_t)(b * Hh + h)) * NQ + 2 * p;
            sum += t[0] + t[1];
        }
        ts_out[row] = sum * (1.f / 12.f);
    }

    const float* xr = x + (size_t)row * d;
    const float4* x4 = reinterpret_cast<const float4*>(xr);
    const float4* g4 = reinterpret_cast<const float4*>(g);
    float s = 0.f, s2 = 0.f;
    for (int i = tid; i < d / 4; i += 128) {
        float4 v = x4[i];
        s  += (v.x + v.y) + (v.z + v.w);
        s2 += (v.x * v.x + v.y * v.y) + (v.z * v.z + v.w * v.w);
    }
    __shared__ float sh[64];
    #pragma unroll
    for (int o = 16; o; o >>= 1) {
        s  += __shfl_xor_sync(0xffffffffu, s,  o);
        s2 += __shfl_xor_sync(0xffffffffu, s2, o);
    }
    int w = tid >> 5;
    if ((tid & 31) == 0) { sh[w] = s; sh[32 + w] = s2; }
    __syncthreads();
    if (tid == 0) {
        float a = 0.f, b = 0.f;
        #pragma unroll
        for (int i = 0; i < 4; i++) { a += sh[i]; b += sh[32 + i]; }
        sh[0] = a; sh[32] = b;
    }
    __syncthreads();
    float mu  = sh[0]  / (float)d;
    float var = sh[32] / (float)d - mu * mu;
    float r = rsqrtf(var + 1e-6f);
    for (int i = tid; i < d / 4; i += 128) {
        float4 v = x4[i];
        float4 gv = g4[i];
        float f0 = (v.x - mu) * r * gv.x;
        float f1 = (v.y - mu) * r * gv.y;
        float f2 = (v.z - mu) * r * gv.z;
        float f3 = (v.w - mu) * r * gv.w;
        __nv_bfloat162 h0 = __floats2bfloat162_rn(f0, f1);
        __nv_bfloat162 h1 = __floats2bfloat162_rn(f2, f3);
        __nv_bfloat162 l0 = __floats2bfloat162_rn(f0 - __bfloat162float(__low2bfloat16(h0)),
                                                  f1 - __bfloat162float(__high2bfloat16(h0)));
        __nv_bfloat162 l1 = __floats2bfloat162_rn(f2 - __bfloat162float(__low2bfloat16(h1)),
                                                  f3 - __bfloat162float(__high2bfloat16(h1)));
        uint2 ph, pl;
        ph.x = *reinterpret_cast<unsigned*>(&h0);
        ph.y = *reinterpret_cast<unsigned*>(&h1);
        pl.x = *reinterpret_cast<unsigned*>(&l0);
        pl.y = *reinterpret_cast<unsigned*>(&l1);
        *reinterpret_cast<uint2*>(yh + (size_t)row * d + i * 4) = ph;
        *reinterpret_cast<uint2*>(yl + (size_t)row * d + i * 4) = pl;
    }
}

// ---------------- merged projection GEMM (Q and KV in one launch) ----------------
__global__ void __launch_bounds__(256, 2)
bgemm_merged(const bf16* __restrict__ A0, const bf16* __restrict__ B0,
             const bf16* __restrict__ A1, const bf16* __restrict__ B1)
{
    __shared__ bf16 As[2][128 * 40];
    __shared__ bf16 Bs[2][32 * 136];
    const int tid = threadIdx.x;
    const int w = tid >> 5, lane = tid & 31;
    const int wm = w >> 1, wn = w & 1;

    int bx = blockIdx.x;
    int mode, m0, n0, N;
    const bf16 *A, *Bm;
    if (bx < 147) {
        mode = 0; A = A0; Bm = B0; N = Dm;
        n0 = (bx % 3) * 128; m0 = (bx / 3) * 128;
    } else {
        bx -= 147;
        mode = 1; A = A1; Bm = B1; N = 2 * Dm;
        n0 = (bx % 6) * 128; m0 = (bx / 6) * 128;
    }
    const int K = Dm;

    const int arow0 = (tid + 0)   >> 2, acol0 = ((tid + 0)   & 3) * 8;
    const int arow1 = (tid + 256) >> 2, acol1 = ((tid + 256) & 3) * 8;
    const int brow0 = (tid + 0)   >> 4, bcol0 = ((tid + 0)   & 15) * 8;
    const int brow1 = (tid + 256) >> 4, bcol1 = ((tid + 256) & 15) * 8;

    float acc[2][8][4];
    #pragma unroll
    for (int i = 0; i < 2; i++)
        #pragma unroll
        for (int j = 0; j < 8; j++)
            #pragma unroll
            for (int t = 0; t < 4; t++) acc[i][j][t] = 0.f;

    const int nit = K / 32;
    cp16(&As[0][arow0 * 40 + acol0], A + (size_t)(m0 + arow0) * K + acol0, 16);
    cp16(&As[0][arow1 * 40 + acol1], A + (size_t)(m0 + arow1) * K + acol1, 16);
    cp16(&Bs[0][brow0 * 136 + bcol0], Bm + (size_t)brow0 * N + n0 + bcol0, 16);
    cp16(&Bs[0][brow1 * 136 + bcol1], Bm + (size_t)brow1 * N + n0 + bcol1, 16);
    cp_commit();

    for (int it = 0; it < nit; it++) {
        if (it + 1 < nit) {
            int k0 = (it + 1) * 32, bn = (it + 1) & 1;
            cp16(&As[bn][arow0 * 40 + acol0], A + (size_t)(m0 + arow0) * K + k0 + acol0, 16);
            cp16(&As[bn][arow1 * 40 + acol1], A + (size_t)(m0 + arow1) * K + k0 + acol1, 16);
            cp16(&Bs[bn][brow0 * 136 + bcol0], Bm + (size_t)(k0 + brow0) * N + n0 + bcol0, 16);
            cp16(&Bs[bn][brow1 * 136 + bcol1], Bm + (size_t)(k0 + brow1) * N + n0 + bcol1, 16);
            cp_commit();
            cp_wait<1>();
        } else {
            cp_wait<0>();
        }
        __syncthreads();
        const bf16* Ab = As[it & 1];
        const bf16* Bb = Bs[it & 1];
        #pragma unroll
        for (int kc = 0; kc < 2; kc++) {
            unsigned af[2][4];
            ldsm4(af[0], lm(&Ab[(wm * 32 + 0)  * 40 + kc * 16], lane, 40));
            ldsm4(af[1], lm(&Ab[(wm * 32 + 16) * 40 + kc * 16], lane, 40));
            #pragma unroll
            for (int p = 0; p < 4; p++) {
                unsigned bfr[4];
                ldsm4t(bfr, lm(&Bb[(kc * 16) * 136 + wn * 64 + p * 16], lane, 136));
                #pragma unroll
                for (int mt = 0; mt < 2; mt++) {
                    mma_bf16(acc[mt][2 * p + 0], af[mt], bfr[0], bfr[1]);
                    mma_bf16(acc[mt][2 * p + 1], af[mt], bfr[2], bfr[3]);
                }
            }
        }
        __syncthreads();
    }

    #pragma unroll
    for (int mt = 0; mt < 2; mt++) {
        #pragma unroll
        for (int half = 0; half < 2; half++) {
            int gr = m0 + wm * 32 + mt * 16 + (lane >> 2) + half * 8;
            #pragma unroll
            for (int nb = 0; nb < 8; nb++) {
                int gc = n0 + wn * 64 + nb * 8 + (lane & 3) * 2;
                float v0 = acc[mt][nb][half * 2 + 0];
                float v1 = acc[mt][nb][half * 2 + 1];
                if (mode == 0) {
                    int b = gr / NQ, q = gr - b * NQ;
                    int hh = gc >> 5, di = gc & 31;
                    __nv_bfloat162 hv = __floats2bfloat162_rn(v0 * (SM_SCALE * LOG2E),
                                                              v1 * (SM_SCALE * LOG2E));
                    *reinterpret_cast<__nv_bfloat162*>(
                        &g_Qb[(((size_t)(b * Hh + hh)) * NQ + q) * DH + di]) = hv;
                } else {
                    int b = gr / NKEY, k = gr - b * NKEY;
                    int two = gc >= Dm;
                    int cc = gc - two * Dm;
                    int hh = cc >> 5, di = cc & 31;
                    size_t off = (((size_t)(b * Hh + hh)) * NKEY + k) * DH + di;
                    if (two) {
                        __half2 hv = __floats2half2_rn(v0, v1);
                        *reinterpret_cast<__half2*>(&g_Vh[off]) = hv;
                    } else {
                        __nv_bfloat162 hv = __floats2bfloat162_rn(v0, v1);
                        *reinterpret_cast<__nv_bfloat162*>(&g_Kb[off]) = hv;
                    }
                }
            }
        }
    }
}

// ---------------- split-bf16 compensated GEMM, 128x128 tiles, BK=16 double-buffered ----------------
template<int MODE>
__global__ void __launch_bounds__(256, 2)
bgemm_split(const bf16* __restrict__ Ah, const bf16* __restrict__ Al,
            const bf16* __restrict__ Bh, const bf16* __restrict__ Bl,
            int M, int N, int K,
            const float* __restrict__ res, const float* __restrict__ rscale,
            float* __restrict__ Cout)
{
    __shared__ bf16 Ash[2][128 * 24];
    __shared__ bf16 Asl[2][128 * 24];
    __shared__ bf16 Bsh[2][16 * 136];
    __shared__ bf16 Bsl[2][16 * 136];
    const int tid = threadIdx.x;
    const int w = tid >> 5, lane = tid & 31;
    const int wm = w >> 1, wn = w & 1;
    const int m0 = blockIdx.y * 128, n0 = blockIdx.x * 128;

    const int arow = tid >> 1, acol = (tid & 1) * 8;
    const int brow = tid >> 4, bcol = (tid & 15) * 8;

    float acc[2][8][4];
    #pragma unroll
    for (int i = 0; i < 2; i++)
        #pragma unroll
        for (int j = 0; j < 8; j++)
            #pragma unroll
            for (int t = 0; t < 4; t++) acc[i][j][t] = 0.f;

    const int nit = K / 16;
    {
        int gr = m0 + arow;
        int ok = (gr < M);
        size_t ra = (size_t)(ok ? gr : 0) * K + acol;
        cp16(&Ash[0][arow * 24 + acol], Ah + ra, ok ? 16 : 0);
        cp16(&Asl[0][arow * 24 + acol], Al + ra, ok ? 16 : 0);
        size_t rb = (size_t)brow * N + n0 + bcol;
        cp16(&Bsh[0][brow * 136 + bcol], Bh + rb, 16);
        cp16(&Bsl[0][brow * 136 + bcol], Bl + rb, 16);
        cp_commit();
    }

    for (int it = 0; it < nit; it++) {
        if (it + 1 < nit) {
            int k0 = (it + 1) * 16, bn = (it + 1) & 1;
            int gr = m0 + arow;
            int ok = (gr < M);
            size_t ra = (size_t)(ok ? gr : 0) * K + k0 + acol;
            cp16(&Ash[bn][arow * 24 + acol], Ah + ra, ok ? 16 : 0);
            cp16(&Asl[bn][arow * 24 + acol], Al + ra, ok ? 16 : 0);
            size_t rb = (size_t)(k0 + brow) * N + n0 + bcol;
            cp16(&Bsh[bn][brow * 136 + bcol], Bh + rb, 16);
            cp16(&Bsl[bn][brow * 136 + bcol], Bl + rb, 16);
            cp_commit();
            cp_wait<1>();
        } else {
            cp_wait<0>();
        }
        __syncthreads();
        const bf16* A_h = Ash[it & 1];
        const bf16* A_l = Asl[it & 1];
        const bf16* B_h = Bsh[it & 1];
        const bf16* B_l = Bsl[it & 1];

        unsigned ah[2][4], al[2][4];
        ldsm4(ah[0], lm(&A_h[(wm * 32 + 0)  * 24], lane, 24));
        ldsm4(ah[1], lm(&A_h[(wm * 32 + 16) * 24], lane, 24));
        ldsm4(al[0], lm(&A_l[(wm * 32 + 0)  * 24], lane, 24));
        ldsm4(al[1], lm(&A_l[(wm * 32 + 16) * 24], lane, 24));
        #pragma unroll
        for (int p = 0; p < 4; p++) {
            unsigned bh4[4], bl4[4];
            ldsm4t(bh4, lm(&B_h[wn * 64 + p * 16], lane, 136));
            ldsm4t(bl4, lm(&B_l[wn * 64 + p * 16], lane, 136));
            #pragma unroll
            for (int mt = 0; mt < 2; mt++) {
                mma_bf16(acc[mt][2 * p + 0], ah[mt], bh4[0], bh4[1]);
                mma_bf16(acc[mt][2 * p + 1], ah[mt], bh4[2], bh4[3]);
                mma_bf16(acc[mt][2 * p + 0], ah[mt], bl4[0], bl4[1]);
                mma_bf16(acc[mt][2 * p + 1], ah[mt], bl4[2], bl4[3]);
                mma_bf16(acc[mt][2 * p + 0], al[mt], bh4[0], bh4[1]);
                mma_bf16(acc[mt][2 * p + 1], al[mt], bh4[2], bh4[3]);
            }
        }
        __syncthreads();
    }

    #pragma unroll
    for (int mt = 0; mt < 2; mt++) {
        #pragma unroll
        for (int half = 0; half < 2; half++) {
            int gr = m0 + wm * 32 + mt * 16 + (lane >> 2) + half * 8;
            if (gr >= M) continue;
            #pragma unroll
            for (int nb = 0; nb < 8; nb++) {
                int gc = n0 + wn * 64 + nb * 8 + (lane & 3) * 2;
                float v0 = acc[mt][nb][half * 2 + 0];
                float v1 = acc[mt][nb][half * 2 + 1];
                if (MODE == 2) {
                    v0 += res[(size_t)gr * N + gc + 0] * rscale[gc + 0];
                    v1 += res[(size_t)gr * N + gc + 1] * rscale[gc + 1];
                }
                *reinterpret_cast<float2*>(&Cout[(size_t)gr * N + gc]) = make_float2(v0, v1);
            }
        }
    }
}

// ---------------- Z-pass: 128-key tile, ones-mma, triple-buffered Q ----------------
__global__ void __launch_bounds__(256)
zpass()
{
    __shared__ bf16 Ks[128 * 40];
    __shared__ bf16 Qs[3][128 * 40];
    const int tid = threadIdx.x;
    const int w = tid >> 5, lane = tid & 31;
    const int k0 = blockIdx.x * 128;
    const int bh = blockIdx.y;

    #pragma unroll
    for (int i = 0; i < 2; i++) {
        int idx = tid + 256 * i;
        int row = idx >> 2, col = (idx & 3) * 8;
        uint4 v = make_uint4(0, 0, 0, 0);
        int kg = k0 + row;
        if (kg < NKEY) v = *reinterpret_cast<const uint4*>(&g_Kb[((size_t)bh * NKEY + kg) * DH + col]);
        *reinterpret_cast<uint4*>(&Ks[row * 40 + col]) = v;
    }
    __syncthreads();

    unsigned aK[2][4];
    ldsm4(aK[0], lm(&Ks[(w * 16) * 40 + 0],  lane, 40));
    ldsm4(aK[1], lm(&Ks[(w * 16) * 40 + 16], lane, 40));

    float zacc[4] = {0.f, 0.f, 0.f, 0.f};

    const int qrow = tid >> 2, qcol = (tid & 3) * 8;
    const int qrow1 = (tid + 256) >> 2, qcol1 = ((tid + 256) & 3) * 8;
    {
        int ok = (qrow < NQ);
        cp16(&Qs[0][qrow * 40 + qcol], &g_Qb[((size_t)bh * NQ + (ok ? qrow : 0)) * DH + qcol], ok ? 16 : 0);
        int ok1 = (qrow1 < NQ);
        cp16(&Qs[0][qrow1 * 40 + qcol1], &g_Qb[((size_t)bh * NQ + (ok1 ? qrow1 : 0)) * DH + qcol1], ok1 ? 16 : 0);
        cp_commit();
    }

    for (int qc = 0; qc < 13; qc++) {
        if (qc + 1 < 13) {
            int qt = (qc + 1) * 128;
            int bn = (qc + 1) % 3;
            int qg = qt + qrow;
            int ok = (qg < NQ);
            cp16(&Qs[bn][qrow * 40 + qcol], &g_Qb[((size_t)bh * NQ + (ok ? qg : 0)) * DH + qcol], ok ? 16 : 0);
            int qg1 = qt + qrow1;
            int ok1 = (qg1 < NQ);
            cp16(&Qs[bn][qrow1 * 40 + qcol1], &g_Qb[((size_t)bh * NQ + (ok1 ? qg1 : 0)) * DH + qcol1], ok1 ? 16 : 0);
            cp_commit();
            cp_wait<1>();
        } else {
            cp_wait<0>();
        }
        __syncthreads();

        const bf16* Qb = Qs[qc % 3];
        int q0 = qc * 128;
        #pragma unroll
        for (int nb2 = 0; nb2 < 8; nb2++) {
            if (q0 + nb2 * 16 >= NQ) continue;
            unsigned bA[4], bB[4];
            ldsm4(bA, lm(&Qb[(nb2 * 16) * 40 + 0],  lane, 40));
            ldsm4(bB, lm(&Qb[(nb2 * 16) * 40 + 16], lane, 40));
            unsigned pa[4];
            #pragma unroll
            for (int s = 0; s < 2; s++) {
                float c[4] = {0.f, 0.f, 0.f, 0.f};
                mma_bf16(c, aK[0], bA[s], bA[s + 2]);
                mma_bf16(c, aK[1], bB[s], bB[s + 2]);
                pa[2 * s + 0] = h2ex2(f2h2(c[0], c[1]));
                pa[2 * s + 1] = h2ex2(f2h2(c[2], c[3]));
            }
            unsigned af[4] = {pa[0], pa[1], pa[2], pa[3]};
            mma_f16(zacc, af, HONES, HONES);
        }
    }

    if ((lane & 3) == 0) {
        int r0 = k0 + w * 16 + (lane >> 2);
        int r1 = r0 + 8;
        g_l2z[(size_t)bh * NKP + r0] = (r0 < NKEY) ? (PBIAS - __log2f(zacc[0])) : -1e30f;
        g_l2z[(size_t)bh * NKP + r1] = (r1 < NKEY) ? (PBIAS - __log2f(zacc[2])) : -1e30f;
    }
}

// ---------------- PV-pass: 4 warps x 32 q-rows; K/V fragments amortized over 2 q-groups ----------------
__global__ void __launch_bounds__(128)
pvpass()
{
    __shared__ bf16 Ks[2][128 * 40];
    __shared__ f16  Vs[2][128 * 40];
    __shared__ float l2zs[2][128];
    const int tid = threadIdx.x;
    const int w = tid >> 5, lane = tid & 31;   // w in 0..3
    const int q0 = blockIdx.x * 128;
    const int bh = blockIdx.y;
    const int b = bh / Hh, hh = bh % Hh;

    // init V ones-columns (cols 32..39; col 32 = 1, rest 0) in both buffers.
    // 128 threads: one full 16B row-chunk each.
    {
        int r = tid;
        f16 vals[8];
        vals[0] = __float2half(1.f);
        #pragma unroll
        for (int j = 1; j < 8; j++) vals[j] = __float2half(0.f);
        *reinterpret_cast<uint4*>(&Vs[0][r * 40 + 32]) = *reinterpret_cast<uint4*>(vals);
        *reinterpret_cast<uint4*>(&Vs[1][r * 40 + 32]) = *reinterpret_cast<uint4*>(vals);
    }

    // stage Q via Ks[0] (128 rows x 32 cols bf16 = 512 x 16B, 4 per thread)
    #pragma unroll
    for (int i = 0; i < 4; i++) {
        int idx = tid + 128 * i;
        int row = idx >> 2, col = (idx & 3) * 8;
        uint4 v = make_uint4(0, 0, 0, 0);
        int qg = q0 + row;
        if (qg < NQ) v = *reinterpret_cast<const uint4*>(&g_Qb[((size_t)bh * NQ + qg) * DH + col]);
        *reinterpret_cast<uint4*>(&Ks[0][row * 40 + col]) = v;
    }
    __syncthreads();
    unsigned aQ[2][2][4];
    #pragma unroll
    for (int g = 0; g < 2; g++) {
        ldsm4(aQ[g][0], lm(&Ks[0][(w * 32 + g * 16) * 40 + 0],  lane, 40));
        ldsm4(aQ[g][1], lm(&Ks[0][(w * 32 + g * 16) * 40 + 16], lane, 40));
    }
    __syncthreads();

    float acc[2][5][4];
    #pragma unroll
    for (int g = 0; g < 2; g++)
        #pragma unroll
        for (int i = 0; i < 5; i++)
            #pragma unroll
            for (int t = 0; t < 4; t++) acc[g][i][t] = 0.f;

    // prologue: tile 0
    #pragma unroll
    for (int i = 0; i < 4; i++) {
        int idx = tid + 128 * i;
        int row = idx >> 2, col = (idx & 3) * 8;
        int kg = row;
        int ok = (kg < NKEY);
        size_t ka = ((size_t)bh * NKEY + (ok ? kg : 0)) * DH + col;
        cp16(&Ks[0][row * 40 + col], &g_Kb[ka], ok ? 16 : 0);
        cp16(&Vs[0][row * 40 + col], &g_Vh[ka], ok ? 16 : 0);
    }
    if (tid < 32) cp16(&l2zs[0][tid * 4], &g_l2z[(size_t)bh * NKP + tid * 4], 16);
    cp_commit();

    for (int kt = 0; kt < 25; kt++) {
        if (kt + 1 < 25) {
            int kb = (kt + 1) * 128;
            int bufn = (kt + 1) & 1;
            #pragma unroll
            for (int i = 0; i < 4; i++) {
                int idx = tid + 128 * i;
                int row = idx >> 2, col = (idx & 3) * 8;
                int kg = kb + row;
                int ok = (kg < NKEY);
                size_t ka = ((size_t)bh * NKEY + (ok ? kg : 0)) * DH + col;
                cp16(&Ks[bufn][row * 40 + col], &g_Kb[ka], ok ? 16 : 0);
                cp16(&Vs[bufn][row * 40 + col], &g_Vh[ka], ok ? 16 : 0);
            }
            if (tid < 32) cp16(&l2zs[bufn][tid * 4], &g_l2z[(size_t)bh * NKP + kb + tid * 4], 16);
            cp_commit();
            cp_wait<1>();
        } else {
            cp_wait<0>();
        }
        __syncthreads();

        const bf16* Kb = Ks[kt & 1];
        const f16*  Vb = Vs[kt & 1];
        const float* lz = l2zs[kt & 1];

        #pragma unroll
        for (int kb2 = 0; kb2 < 8; kb2++) {
            unsigned bA[4], bB[4];
            ldsm4(bA, lm(&Kb[(kb2 * 16) * 40 + 0],  lane, 40));
            ldsm4(bB, lm(&Kb[(kb2 * 16) * 40 + 16], lane, 40));
            int cb = kb2 * 16 + (lane & 3) * 2;
            float b0 = lz[cb], b1 = lz[cb + 1], b2 = lz[cb + 8], b3 = lz[cb + 9];
            unsigned pa[2][4];
            #pragma unroll
            for (int g = 0; g < 2; g++) {
                float c0[4] = {b0, b1, b0, b1};
                float c1[4] = {b2, b3, b2, b3};
                mma_bf16(c0, aQ[g][0], bA[0], bA[2]);
                mma_bf16(c0, aQ[g][1], bB[0], bB[2]);
                mma_bf16(c1, aQ[g][0], bA[1], bA[3]);
                mma_bf16(c1, aQ[g][1], bB[1], bB[3]);
                pa[g][0] = h2ex2(f2h2(c0[0], c0[1]));
                pa[g][1] = h2ex2(f2h2(c0[2], c0[3]));
                pa[g][2] = h2ex2(f2h2(c1[0], c1[1]));
                pa[g][3] = h2ex2(f2h2(c1[2], c1[3]));
            }
            unsigned v0[4], v1[4], v2[2];
            ldsm4t(v0, lm(&Vb[(kb2 * 16) * 40 + 0],  lane, 40));
            ldsm4t(v1, lm(&Vb[(kb2 * 16) * 40 + 16], lane, 40));
            ldsm2t(v2, lm(&Vb[(kb2 * 16) * 40 + 32], lane, 40));
            #pragma unroll
            for (int g = 0; g < 2; g++) {
                mma_f16(acc[g][0], pa[g], v0[0], v0[1]);
                mma_f16(acc[g][1], pa[g], v0[2], v0[3]);
                mma_f16(acc[g][2], pa[g], v1[0], v1[1]);
                mma_f16(acc[g][3], pa[g], v1[2], v1[3]);
                mma_f16(acc[g][4], pa[g], v2[0], v2[1]);
            }
        }
        __syncthreads();
    }

    int src = lane & 28;
    #pragma unroll
    for (int g = 0; g < 2; g++) {
        float den0 = __shfl_sync(0xffffffffu, acc[g][4][0], src);
        float den1 = __shfl_sync(0xffffffffu, acc[g][4][2], src);
        float inv0 = 1.f / (den0 + PSCALE * 1e-6f);
        float inv1 = 1.f / (den1 + PSCALE * 1e-6f);

        int qr0 = q0 + w * 32 + g * 16 + (lane >> 2);
        int qr1 = qr0 + 8;
        if (qr0 < NQ) {
            size_t base = ((size_t)b * NQ + qr0) * Dm + hh * DH + (lane & 3) * 2;
            #pragma unroll
            for (int nb = 0; nb < 4; nb++) {
                float v0 = acc[g][nb][0] * inv0, v1 = acc[g][nb][1] * inv0;
                __nv_bfloat162 h = __floats2bfloat162_rn(v0, v1);
                __nv_bfloat162 l = __floats2bfloat162_rn(v0 - __bfloat162float(__low2bfloat16(h)),
                                                         v1 - __bfloat162float(__high2bfloat16(h)));
                *reinterpret_cast<__nv_bfloat162*>(&g_c2h[base + nb * 8]) = h;
                *reinterpret_cast<__nv_bfloat162*>(&g_c2l[base + nb * 8]) = l;
            }
            if ((lane & 3) == 0) g_tsh[(size_t)bh * NQ + qr0] = den0 * (1.f / PSCALE);
        }
        if (qr1 < NQ) {
            size_t base = ((size_t)b * NQ + qr1) * Dm + hh * DH + (lane & 3) * 2;
            #pragma unroll
            for (int nb = 0; nb < 4; nb++) {
                float v0 = acc[g][nb][2] * inv1, v1 = acc[g][nb][3] * inv1;
                __nv_bfloat162 h = __floats2bfloat162_rn(v0, v1);
                __nv_bfloat162 l = __floats2bfloat162_rn(v0 - __bfloat162float(__low2bfloat16(h)),
                                                         v1 - __bfloat162float(__high2bfloat16(h)));
                *reinterpret_cast<__nv_bfloat162*>(&g_c2h[base + nb * 8]) = h;
                *reinterpret_cast<__nv_bfloat162*>(&g_c2l[base + nb * 8]) = l;
            }
            if ((lane & 3) == 0) g_tsh[(size_t)bh * NQ + qr1] = den1 * (1.f / PSCALE);
        }
    }
}

// ---------------- launch ----------------
extern "C" void kernel_launch(void* const* d_in, const int* in_sizes, int n_in,
                              void* d_out, int out_size)
{
    const float* x         = (const float*)d_in[0];
    const float* clusters  = (const float*)d_in[1];
    const float* g1        = (const float*)d_in[2];
    const float* Wq        = (const float*)d_in[3];
    const float* Wkv       = (const float*)d_in[4];
    const float* Wo        = (const float*)d_in[5];
    const float* res_scale = (const float*)d_in[6];
    const float* g2        = (const float*)d_in[7];
    const float* Wproj     = (const float*)d_in[8];
    float* out = (float*)d_out;

    bf16 *p_xnb, *p_cnb, *p_Wqb, *p_Wkvb, *p_Woh, *p_Wol, *p_Wph, *p_Wpl;
    bf16 *p_c2h, *p_c2l, *p_ynh, *p_ynl;
    float *p_y0;
    cudaGetSymbolAddress((void**)&p_xnb, g_xnb);
    cudaGetSymbolAddress((void**)&p_cnb, g_cnb);
    cudaGetSymbolAddress((void**)&p_Wqb, g_Wqb);
    cudaGetSymbolAddress((void**)&p_Wkvb, g_Wkvb);
    cudaGetSymbolAddress((void**)&p_Woh, g_Woh);
    cudaGetSymbolAddress((void**)&p_Wol, g_Wol);
    cudaGetSymbolAddress((void**)&p_Wph, g_Wph);
    cudaGetSymbolAddress((void**)&p_Wpl, g_Wpl);
    cudaGetSymbolAddress((void**)&p_c2h, g_c2h);
    cudaGetSymbolAddress((void**)&p_c2l, g_c2l);
    cudaGetSymbolAddress((void**)&p_ynh, g_ynh);
    cudaGetSymbolAddress((void**)&p_ynl, g_ynl);
    cudaGetSymbolAddress((void**)&p_y0, g_y0);

    prep_kernel<<<NB_LN + NB_CVT, 128>>>(x, clusters, g1, Wq, Wkv, Wo, Wproj);

    bgemm_merged<<<735, 256>>>(p_cnb, p_Wqb, p_xnb, p_Wkvb);

    zpass<<<dim3(25, BH), 256>>>();
    pvpass<<<dim3(13, BH), 128>>>();

    bgemm_split<2><<<dim3(3, 49), 256>>>(p_c2h, p_c2l, p_Woh, p_Wol,
                                         Bz * NQ, Dm, Dm, clusters, res_scale, p_y0);
    ln_split_kernel<<<Bz * NP, 128>>>(p_y0, g2, p_ynh, p_ynl, out + (size_t)Bz * NP * D2);
    bgemm_split<3><<<dim3(6, 25), 256>>>(p_ynh, p_ynl, p_Wph, p_Wpl,
                                         Bz * NP, D2, D2, nullptr, nullptr, out);
}